// round 12
// baseline (speedup 1.0000x reference)
#include <cuda_runtime.h>

typedef unsigned long long ull;

#define Bsz  8192
#define Tlen 1024
#define NOUT 1019
#define UPAD 24
#define Sc   2.88539008177792681472f   // 2 * log2(e)

// u channel, transposed AND duplicated: g_uD[t*Bsz + b] = (u, u) as f32x2.
// Rows t >= 1024 are never written (.bss zero); they only feed accumulators
// whose outputs are never stored.
__device__ ull g_uD[(Tlen + UPAD) * Bsz];

// ---------------- f32x2 / MUFU helpers ----------------
__device__ __forceinline__ ull f2fma(ull a, ull b, ull c) {
    ull d; asm("fma.rn.f32x2 %0, %1, %2, %3;" : "=l"(d) : "l"(a), "l"(b), "l"(c)); return d;
}
__device__ __forceinline__ ull fpack(float lo, float hi) {
    ull r; asm("mov.b64 %0, {%1, %2};" : "=l"(r) : "f"(lo), "f"(hi)); return r;
}
__device__ __forceinline__ void funpack(ull v, float& lo, float& hi) {
    asm("mov.b64 {%0, %1}, %2;" : "=f"(lo), "=f"(hi) : "l"(v));
}
__device__ __forceinline__ float flow(ull v) {
    float lo, hi; funpack(v, lo, hi); return lo;
}
__device__ __forceinline__ float fex2(float x) {
    float r; asm("ex2.approx.f32 %0, %1;" : "=f"(r) : "f"(x)); return r;
}
__device__ __forceinline__ float frcp(float x) {
    float r; asm("rcp.approx.f32 %0, %1;" : "=f"(r) : "f"(x)); return r;
}

// ---------------- kernel 1: transpose + duplicate u channel ----------------
__global__ void transpose_u(const float* __restrict__ traj) {
    __shared__ float tile[32][33];
    int tx = threadIdx.x, ty = threadIdx.y;
    int t0 = blockIdx.x * 32, b0 = blockIdx.y * 32;
    tile[ty][tx] = traj[((size_t)(b0 + ty) * Tlen + (t0 + tx)) * 3];
    __syncthreads();
    float v = tile[tx][ty];
    g_uD[(size_t)(t0 + ty) * Bsz + (b0 + tx)] = fpack(v, v);
}

// ---------------- per-lane weights (each lane owns hidden pair + 1 scalar) ----------------
// tanh(z) = 1 - 2*rcp(exp2(Sc*z)+1); W1,b1 pre-scaled by Sc; affine folded into
// layer 2 (w2 -> -2*w2, b2 += sum w2). Layer 2 computed as scalar partials per lane.
struct Lw {
    ull   wu_p[5], wc1_p[5], wc2_p[5], b1_p;   // packed pair (2 hidden units)
    float wu_s[5], wc1_s[5], wc2_s[5], b1_s;   // scalar hidden unit
    float w20[3], w21[3];                      // layer-2 coeffs of the 3 owned units
    float b20h, b21h;                          // folded bias (only on half 0)
};

// full 6-hidden MLP for the prologue (uniform on both lanes; reads weights from global)
__device__ __forceinline__ void mlp6(const float* __restrict__ W1g, const float* __restrict__ b1g,
                                     const float* __restrict__ W2g, float b20f, float b21f,
                                     const float uu[5], const float c1[5], const float c2[5],
                                     float& o0, float& o1) {
    float r[6];
#pragma unroll
    for (int h = 0; h < 6; ++h) {
        float z = b1g[h];
#pragma unroll
        for (int i = 0; i < 5; ++i) z = fmaf(W1g[h * 15 + i],      uu[i], z);
#pragma unroll
        for (int i = 0; i < 5; ++i) z = fmaf(W1g[h * 15 + 5 + i],  c1[i], z);
#pragma unroll
        for (int i = 0; i < 5; ++i) z = fmaf(W1g[h * 15 + 10 + i], c2[i], z);
        r[h] = frcp(fex2(z * Sc) + 1.0f);
    }
    o0 = b20f; o1 = b21f;
#pragma unroll
    for (int h = 0; h < 6; ++h) {
        o0 = fmaf(-2.0f * W2g[h],     r[h], o0);
        o1 = fmaf(-2.0f * W2g[6 + h], r[h], o1);
    }
}

// ---------------- one rollout step, all ring indices compile-time ----------------
// t = base + J. z(t) lives in (acc_p,acc_s)[J%5]; fresh z(t+5) rebuilt into same slot.
// uq[(J+i)%10] holds (u(t+5+i))x2; prefetch u(t+15) into slot J%10.
template<int J>
__device__ __forceinline__ void step(ull acc_p[5], float acc_s[5], ull uq[10], const Lw& w,
                                     const ull* __restrict__ up, ull* __restrict__ opd,
                                     int base, int half) {
    constexpr int F = J % 5;

    // finish: own 3 hidden units -> scalar layer-2 partials -> butterfly
    float z0, z1; funpack(acc_p[F], z0, z1);
    float r0 = frcp(fex2(z0) + 1.0f);
    float r1 = frcp(fex2(z1) + 1.0f);
    float rs = frcp(fex2(acc_s[F]) + 1.0f);
    float part0 = fmaf(w.w20[2], rs, fmaf(w.w20[1], r1, fmaf(w.w20[0], r0, w.b20h)));
    float part1 = fmaf(w.w21[2], rs, fmaf(w.w21[1], r1, fmaf(w.w21[0], r0, w.b21h)));
    float o0 = part0 + __shfl_xor_sync(0xFFFFFFFFu, part0, 1);
    float o1 = part1 + __shfl_xor_sync(0xFFFFFFFFu, part1, 1);
    ull o = fpack(o0, o1);
    if ((half == 0) && (base + J < NOUT)) opd[J] = o;
    ull cp1 = fpack(o0, o0), cp2 = fpack(o1, o1);

    // scatter pred(t) into z(t+1)..z(t+4); z(t+1) first (next step's critical input)
#pragma unroll
    for (int d = 1; d <= 4; ++d) {
        const int s = (F + d) % 5, pos = 5 - d;
        acc_p[s] = f2fma(w.wc1_p[pos], cp1, acc_p[s]);
        acc_p[s] = f2fma(w.wc2_p[pos], cp2, acc_p[s]);
        acc_s[s] = fmaf(w.wc1_s[pos], o0, fmaf(w.wc2_s[pos], o1, acc_s[s]));
    }

    // fresh z(t+5): bias + 5 u terms + pred(t) at window pos 0
    ull u5 = uq[J % 10];                 // u(t+5), read before overwrite
    uq[J % 10] = up[(size_t)J * Bsz];    // prefetch u(t+15), first used 6 steps later
    ull ap   = f2fma(w.wu_p[0], u5, w.b1_p);
    float as = fmaf(w.wu_s[0], flow(u5), w.b1_s);
#pragma unroll
    for (int i = 1; i < 5; ++i) {
        ull uv = uq[(J + i) % 10];
        ap = f2fma(w.wu_p[i], uv, ap);
        as = fmaf(w.wu_s[i], flow(uv), as);
    }
    ap = f2fma(w.wc1_p[0], cp1, ap);
    ap = f2fma(w.wc2_p[0], cp2, ap);
    as = fmaf(w.wc1_s[0], o0, fmaf(w.wc2_s[0], o1, as));
    acc_p[F] = ap;
    acc_s[F] = as;
}

// ---------------- kernel 2: the rollout (2 lanes per batch row) ----------------
__global__ void __launch_bounds__(32, 1)
rollout(const float* __restrict__ traj,
        const float* __restrict__ W1g, const float* __restrict__ b1g,
        const float* __restrict__ W2g, const float* __restrict__ b2g,
        float* __restrict__ out) {
    const int lane = threadIdx.x;
    const int half = lane & 1;
    const int b    = blockIdx.x * 16 + (lane >> 1);

    // layer-2 bias fold (needed by both prologue and main loop)
    float s0 = 0.f, s1 = 0.f;
#pragma unroll
    for (int j = 0; j < 6; ++j) { s0 += W2g[j]; s1 += W2g[6 + j]; }
    const float b20f = b2g[0] + s0, b21f = b2g[1] + s1;

    // per-lane main-loop weights: pair rows (2*half, 2*half+1), scalar row 4+half
    const int pr0 = 2 * half, pr1 = 2 * half + 1, sc = 4 + half;
    Lw w;
#pragma unroll
    for (int i = 0; i < 5; ++i) {
        w.wu_p [i] = fpack(W1g[pr0 * 15 + i     ] * Sc, W1g[pr1 * 15 + i     ] * Sc);
        w.wc1_p[i] = fpack(W1g[pr0 * 15 + 5 + i ] * Sc, W1g[pr1 * 15 + 5 + i ] * Sc);
        w.wc2_p[i] = fpack(W1g[pr0 * 15 + 10 + i] * Sc, W1g[pr1 * 15 + 10 + i] * Sc);
        w.wu_s [i] = W1g[sc * 15 + i     ] * Sc;
        w.wc1_s[i] = W1g[sc * 15 + 5 + i ] * Sc;
        w.wc2_s[i] = W1g[sc * 15 + 10 + i] * Sc;
    }
    w.b1_p = fpack(b1g[pr0] * Sc, b1g[pr1] * Sc);
    w.b1_s = b1g[sc] * Sc;
    w.w20[0] = -2.f * W2g[pr0]; w.w20[1] = -2.f * W2g[pr1]; w.w20[2] = -2.f * W2g[sc];
    w.w21[0] = -2.f * W2g[6 + pr0]; w.w21[1] = -2.f * W2g[6 + pr1]; w.w21[2] = -2.f * W2g[6 + sc];
    w.b20h = (half == 0) ? b20f : 0.f;
    w.b21h = (half == 0) ? b21f : 0.f;

    // packed u for seeds (+ scalar views) and ground-truth c1/c2 for prologue
    ull pu[20];
#pragma unroll
    for (int k = 0; k < 20; ++k) pu[k] = g_uD[(size_t)k * Bsz + b];
    float u[12];
#pragma unroll
    for (int k = 0; k < 12; ++k) u[k] = flow(pu[k]);
    float g1[5], g2[5];
#pragma unroll
    for (int k = 0; k < 5; ++k) {
        g1[k] = traj[((size_t)b * Tlen + k) * 3 + 1];
        g2[k] = traj[((size_t)b * Tlen + k) * 3 + 2];
    }

    ull* op = reinterpret_cast<ull*>(out) + (size_t)b * NOUT;  // float2 per step

    // Prologue — replicates the reference's index pattern exactly (computed
    // identically on both lanes; lane 0 stores).
    float p0[5], p1[5];
    {
        float uu[5] = {u[0], u[1], u[2], u[3], u[4]},
              c1[5] = {g1[0], g1[1], g1[2], g1[3], g1[4]},
              c2[5] = {g2[0], g2[1], g2[2], g2[3], g2[4]};
        mlp6(W1g, b1g, W2g, b20f, b21f, uu, c1, c2, p0[0], p1[0]);
    }
    {
        float uu[5] = {u[1], u[2], u[3], u[4], u[5]},
              c1[5] = {g1[1], g1[2], g1[3], g1[4], p0[0]},
              c2[5] = {g2[1], g2[2], g2[3], g2[4], p1[0]};
        mlp6(W1g, b1g, W2g, b20f, b21f, uu, c1, c2, p0[1], p1[1]);
    }
    {
        float uu[5] = {u[2], u[3], u[4], u[6], u[7]},
              c1[5] = {g1[2], g1[3], g1[4], p0[0], p0[1]},
              c2[5] = {g2[2], g2[3], g2[4], p1[0], p1[1]};
        mlp6(W1g, b1g, W2g, b20f, b21f, uu, c1, c2, p0[2], p1[2]);
    }
    {
        float uu[5] = {u[3], u[4], u[7], u[8], u[9]},
              c1[5] = {g1[3], g1[4], p0[0], p0[1], p0[2]},
              c2[5] = {g2[3], g2[4], p1[0], p1[1], p1[2]};
        mlp6(W1g, b1g, W2g, b20f, b21f, uu, c1, c2, p0[3], p1[3]);
    }
    {
        float uu[5] = {u[4], u[8], u[9], u[10], u[11]},
              c1[5] = {g1[4], p0[0], p0[1], p0[2], p0[3]},
              c2[5] = {g2[4], p1[0], p1[1], p1[2], p1[3]};
        mlp6(W1g, b1g, W2g, b20f, b21f, uu, c1, c2, p0[4], p1[4]);
    }
    if (half == 0) {
#pragma unroll
        for (int k = 0; k < 5; ++k) op[k] = fpack(p0[k], p1[k]);
    }

    // eager accumulators for own units: (acc_p,acc_s)[k] = partial z(5+k)
    ull P0[5], P1[5];
#pragma unroll
    for (int j = 0; j < 5; ++j) { P0[j] = fpack(p0[j], p0[j]); P1[j] = fpack(p1[j], p1[j]); }
    ull acc_p[5]; float acc_s[5];
#pragma unroll
    for (int k = 0; k < 5; ++k) {
        ull ap = w.b1_p; float as = w.b1_s;
#pragma unroll
        for (int i = 0; i < 5; ++i) {
            ap = f2fma(w.wu_p[i], pu[5 + k + i], ap);
            as = fmaf(w.wu_s[i], flow(pu[5 + k + i]), as);
        }
#pragma unroll
        for (int j = 0; j < 5; ++j) {
            if (j >= k) {
                int pos = j - k;
                ap = f2fma(w.wc1_p[pos], P0[j], ap);
                ap = f2fma(w.wc2_p[pos], P1[j], ap);
                as = fmaf(w.wc1_s[pos], p0[j], fmaf(w.wc2_s[pos], p1[j], as));
            }
        }
        acc_p[k] = ap; acc_s[k] = as;
    }

    // u ring: uq[j] = (u(10+j))x2
    ull uq[10];
#pragma unroll
    for (int j = 0; j < 10; ++j) uq[j] = pu[10 + j];

    // main loop: t = base + J, covers t = 5..1024; stores predicated to t < 1019.
    const ull* up = g_uD + (size_t)20 * Bsz + b;  // up[J*Bsz] = u(base + J + 15)
    ull* opd = op + 5;
    for (int base = 5; base < 1025; base += 10) {
        step<0>(acc_p, acc_s, uq, w, up, opd, base, half);
        step<1>(acc_p, acc_s, uq, w, up, opd, base, half);
        step<2>(acc_p, acc_s, uq, w, up, opd, base, half);
        step<3>(acc_p, acc_s, uq, w, up, opd, base, half);
        step<4>(acc_p, acc_s, uq, w, up, opd, base, half);
        step<5>(acc_p, acc_s, uq, w, up, opd, base, half);
        step<6>(acc_p, acc_s, uq, w, up, opd, base, half);
        step<7>(acc_p, acc_s, uq, w, up, opd, base, half);
        step<8>(acc_p, acc_s, uq, w, up, opd, base, half);
        step<9>(acc_p, acc_s, uq, w, up, opd, base, half);
        up += (size_t)10 * Bsz;
        opd += 10;
    }
}

extern "C" void kernel_launch(void* const* d_in, const int* in_sizes, int n_in,
                              void* d_out, int out_size) {
    (void)in_sizes; (void)n_in; (void)out_size;
    const float* traj = (const float*)d_in[0];
    const float* W1   = (const float*)d_in[1];
    const float* b1   = (const float*)d_in[2];
    const float* W2   = (const float*)d_in[3];
    const float* b2   = (const float*)d_in[4];

    transpose_u<<<dim3(Tlen / 32, Bsz / 32), dim3(32, 32)>>>(traj);
    rollout<<<(2 * Bsz) / 32, 32>>>(traj, W1, b1, W2, b2, (float*)d_out);
}

// round 14
// speedup vs baseline: 1.0431x; 1.0431x over previous
#include <cuda_runtime.h>

typedef unsigned long long ull;

#define Bsz  8192
#define Tlen 1024
#define NOUT 1019
#define UPAD 24
#define Sc   2.88539008177792681472f   // 2 * log2(e)

// u channel, transposed AND duplicated: g_uD[t*Bsz + b] = (u, u) as f32x2.
// Rows t >= 1024 are never written (.bss zero); they only feed accumulators
// whose outputs are never stored.
__device__ ull g_uD[(Tlen + UPAD) * Bsz];

// ---------------- f32x2 / MUFU helpers ----------------
__device__ __forceinline__ ull f2fma(ull a, ull b, ull c) {
    ull d; asm("fma.rn.f32x2 %0, %1, %2, %3;" : "=l"(d) : "l"(a), "l"(b), "l"(c)); return d;
}
__device__ __forceinline__ ull fpack(float lo, float hi) {
    ull r; asm("mov.b64 %0, {%1, %2};" : "=l"(r) : "f"(lo), "f"(hi)); return r;
}
__device__ __forceinline__ void funpack(ull v, float& lo, float& hi) {
    asm("mov.b64 {%0, %1}, %2;" : "=f"(lo), "=f"(hi) : "l"(v));
}
__device__ __forceinline__ float flow(ull v) {
    float lo, hi; funpack(v, lo, hi); return lo;
}
__device__ __forceinline__ float fex2(float x) {
    float r; asm("ex2.approx.f32 %0, %1;" : "=f"(r) : "f"(x)); return r;
}
__device__ __forceinline__ float frcp(float x) {
    float r; asm("rcp.approx.f32 %0, %1;" : "=f"(r) : "f"(x)); return r;
}

// ---------------- kernel 1: transpose + duplicate u channel ----------------
__global__ void transpose_u(const float* __restrict__ traj) {
    __shared__ float tile[32][33];
    int tx = threadIdx.x, ty = threadIdx.y;
    int t0 = blockIdx.x * 32, b0 = blockIdx.y * 32;
    tile[ty][tx] = traj[((size_t)(b0 + ty) * Tlen + (t0 + tx)) * 3];
    __syncthreads();
    float v = tile[tx][ty];
    g_uD[(size_t)(t0 + ty) * Bsz + (b0 + tx)] = fpack(v, v);
}

// ---------------- per-lane weights (each lane owns hidden pair + 1 scalar) ----------------
// tanh(z) = 1 - 2*rcp(exp2(Sc*z)+1); W1,b1 pre-scaled by Sc; affine folded into
// layer 2 (w2 -> -2*w2, b2 += sum w2). Layer 2 computed as scalar partials per lane.
struct Lw {
    ull   wu_p[5], wc1_p[5], wc2_p[5], b1_p;   // packed pair (2 hidden units)
    float wu_s[5], wc1_s[5], wc2_s[5], b1_s;   // scalar hidden unit
    float w20[3], w21[3];                      // layer-2 coeffs of the 3 owned units
    float b20h, b21h;                          // folded bias (only on half 0)
};

// full 6-hidden MLP for the prologue (uniform on both lanes; reads weights from global)
__device__ __forceinline__ void mlp6(const float* __restrict__ W1g, const float* __restrict__ b1g,
                                     const float* __restrict__ W2g, float b20f, float b21f,
                                     const float uu[5], const float c1[5], const float c2[5],
                                     float& o0, float& o1) {
    float r[6];
#pragma unroll
    for (int h = 0; h < 6; ++h) {
        float z = b1g[h];
#pragma unroll
        for (int i = 0; i < 5; ++i) z = fmaf(W1g[h * 15 + i],      uu[i], z);
#pragma unroll
        for (int i = 0; i < 5; ++i) z = fmaf(W1g[h * 15 + 5 + i],  c1[i], z);
#pragma unroll
        for (int i = 0; i < 5; ++i) z = fmaf(W1g[h * 15 + 10 + i], c2[i], z);
        r[h] = frcp(fex2(z * Sc) + 1.0f);
    }
    o0 = b20f; o1 = b21f;
#pragma unroll
    for (int h = 0; h < 6; ++h) {
        o0 = fmaf(-2.0f * W2g[h],     r[h], o0);
        o1 = fmaf(-2.0f * W2g[6 + h], r[h], o1);
    }
}

// ---------------- one rollout step (deferred-scatter form) ----------------
// Carries o_prev = pred(t-1) (o0/o1 scalars + cp1/cp2 broadcast packs).
// At entry, acc[k] = z(t+k) partial, containing all u terms and all pred terms
// EXCEPT those of pred(t-1). Step t:
//   1. complete z(t) with o_prev's pos-4 term (critical, short)
//   2. tanh -> layer-2 partials -> shfl butterfly -> o(t)        (the chain)
//   3. in the chain's shadow: scatter o_prev into z(t+1..t+4) (pos 3..0)
//      and rebuild slot F as z(t+5) = bias + 5 u terms (no pred terms yet)
template<int J>
__device__ __forceinline__ void step(ull acc_p[5], float acc_s[5], ull uq[10], const Lw& w,
                                     const ull* __restrict__ up, ull* __restrict__ opd,
                                     int base, int half,
                                     float& o0, float& o1, ull& cp1, ull& cp2) {
    constexpr int F = J % 5;

    // 1. complete z(t): pos-4 contribution of pred(t-1)
    ull apF = f2fma(w.wc1_p[4], cp1, acc_p[F]);
    apF     = f2fma(w.wc2_p[4], cp2, apF);
    float asF = fmaf(w.wc1_s[4], o0, fmaf(w.wc2_s[4], o1, acc_s[F]));

    // 2. tanh + layer-2 partials (critical chain up to shfl)
    float z0, z1; funpack(apF, z0, z1);
    float r0 = frcp(fex2(z0) + 1.0f);
    float r1 = frcp(fex2(z1) + 1.0f);
    float rs = frcp(fex2(asF) + 1.0f);
    float part0 = fmaf(w.w20[2], rs, fmaf(w.w20[1], r1, fmaf(w.w20[0], r0, w.b20h)));
    float part1 = fmaf(w.w21[2], rs, fmaf(w.w21[1], r1, fmaf(w.w21[0], r0, w.b21h)));

    // 3. shadow work — depends only on o_prev / u ring, not on o(t)
#pragma unroll
    for (int d = 1; d <= 4; ++d) {
        const int s = (F + d) % 5, pos = 4 - d;
        acc_p[s] = f2fma(w.wc1_p[pos], cp1, acc_p[s]);
        acc_p[s] = f2fma(w.wc2_p[pos], cp2, acc_p[s]);
        acc_s[s] = fmaf(w.wc1_s[pos], o0, fmaf(w.wc2_s[pos], o1, acc_s[s]));
    }
    ull u5 = uq[J % 10];                 // u(t+5), read before overwrite
    uq[J % 10] = up[(size_t)J * Bsz];    // prefetch u(t+15), first used 6 steps later
    ull ap   = f2fma(w.wu_p[0], u5, w.b1_p);
    float as = fmaf(w.wu_s[0], flow(u5), w.b1_s);
#pragma unroll
    for (int i = 1; i < 5; ++i) {
        ull uv = uq[(J + i) % 10];
        ap = f2fma(w.wu_p[i], uv, ap);
        as = fmaf(w.wu_s[i], flow(uv), as);
    }
    acc_p[F] = ap;   // now holds z(t+5) partial (u terms only)
    acc_s[F] = as;

    // chain tail: butterfly completes o(t)
    float no0 = part0 + __shfl_xor_sync(0xFFFFFFFFu, part0, 1);
    float no1 = part1 + __shfl_xor_sync(0xFFFFFFFFu, part1, 1);
    if ((half == 0) && (base + J < NOUT)) opd[J] = fpack(no0, no1);
    o0 = no0; o1 = no1;
    cp1 = fpack(no0, no0);
    cp2 = fpack(no1, no1);
}

// ---------------- kernel 2: the rollout (2 lanes per batch row) ----------------
// 128-thread blocks: 4 warps -> wid%4 spreads one warp onto each SMSP.
__global__ void __launch_bounds__(128, 1)
rollout(const float* __restrict__ traj,
        const float* __restrict__ W1g, const float* __restrict__ b1g,
        const float* __restrict__ W2g, const float* __restrict__ b2g,
        float* __restrict__ out) {
    const int lane = threadIdx.x;
    const int half = lane & 1;
    const int b    = blockIdx.x * 64 + (lane >> 1);

    // layer-2 bias fold (needed by both prologue and main loop)
    float s0 = 0.f, s1 = 0.f;
#pragma unroll
    for (int j = 0; j < 6; ++j) { s0 += W2g[j]; s1 += W2g[6 + j]; }
    const float b20f = b2g[0] + s0, b21f = b2g[1] + s1;

    // per-lane main-loop weights: pair rows (2*half, 2*half+1), scalar row 4+half
    const int pr0 = 2 * half, pr1 = 2 * half + 1, sc = 4 + half;
    Lw w;
#pragma unroll
    for (int i = 0; i < 5; ++i) {
        w.wu_p [i] = fpack(W1g[pr0 * 15 + i     ] * Sc, W1g[pr1 * 15 + i     ] * Sc);
        w.wc1_p[i] = fpack(W1g[pr0 * 15 + 5 + i ] * Sc, W1g[pr1 * 15 + 5 + i ] * Sc);
        w.wc2_p[i] = fpack(W1g[pr0 * 15 + 10 + i] * Sc, W1g[pr1 * 15 + 10 + i] * Sc);
        w.wu_s [i] = W1g[sc * 15 + i     ] * Sc;
        w.wc1_s[i] = W1g[sc * 15 + 5 + i ] * Sc;
        w.wc2_s[i] = W1g[sc * 15 + 10 + i] * Sc;
    }
    w.b1_p = fpack(b1g[pr0] * Sc, b1g[pr1] * Sc);
    w.b1_s = b1g[sc] * Sc;
    w.w20[0] = -2.f * W2g[pr0]; w.w20[1] = -2.f * W2g[pr1]; w.w20[2] = -2.f * W2g[sc];
    w.w21[0] = -2.f * W2g[6 + pr0]; w.w21[1] = -2.f * W2g[6 + pr1]; w.w21[2] = -2.f * W2g[6 + sc];
    w.b20h = (half == 0) ? b20f : 0.f;
    w.b21h = (half == 0) ? b21f : 0.f;

    // packed u for seeds (+ scalar views) and ground-truth c1/c2 for prologue
    ull pu[20];
#pragma unroll
    for (int k = 0; k < 20; ++k) pu[k] = g_uD[(size_t)k * Bsz + b];
    float u[12];
#pragma unroll
    for (int k = 0; k < 12; ++k) u[k] = flow(pu[k]);
    float g1[5], g2[5];
#pragma unroll
    for (int k = 0; k < 5; ++k) {
        g1[k] = traj[((size_t)b * Tlen + k) * 3 + 1];
        g2[k] = traj[((size_t)b * Tlen + k) * 3 + 2];
    }

    ull* op = reinterpret_cast<ull*>(out) + (size_t)b * NOUT;  // float2 per step

    // Prologue — replicates the reference's index pattern exactly (computed
    // identically on both lanes; lane 0 stores).
    float p0[5], p1[5];
    {
        float uu[5] = {u[0], u[1], u[2], u[3], u[4]},
              c1[5] = {g1[0], g1[1], g1[2], g1[3], g1[4]},
              c2[5] = {g2[0], g2[1], g2[2], g2[3], g2[4]};
        mlp6(W1g, b1g, W2g, b20f, b21f, uu, c1, c2, p0[0], p1[0]);
    }
    {
        float uu[5] = {u[1], u[2], u[3], u[4], u[5]},
              c1[5] = {g1[1], g1[2], g1[3], g1[4], p0[0]},
              c2[5] = {g2[1], g2[2], g2[3], g2[4], p1[0]};
        mlp6(W1g, b1g, W2g, b20f, b21f, uu, c1, c2, p0[1], p1[1]);
    }
    {
        float uu[5] = {u[2], u[3], u[4], u[6], u[7]},
              c1[5] = {g1[2], g1[3], g1[4], p0[0], p0[1]},
              c2[5] = {g2[2], g2[3], g2[4], p1[0], p1[1]};
        mlp6(W1g, b1g, W2g, b20f, b21f, uu, c1, c2, p0[2], p1[2]);
    }
    {
        float uu[5] = {u[3], u[4], u[7], u[8], u[9]},
              c1[5] = {g1[3], g1[4], p0[0], p0[1], p0[2]},
              c2[5] = {g2[3], g2[4], p1[0], p1[1], p1[2]};
        mlp6(W1g, b1g, W2g, b20f, b21f, uu, c1, c2, p0[3], p1[3]);
    }
    {
        float uu[5] = {u[4], u[8], u[9], u[10], u[11]},
              c1[5] = {g1[4], p0[0], p0[1], p0[2], p0[3]},
              c2[5] = {g2[4], p1[0], p1[1], p1[2], p1[3]};
        mlp6(W1g, b1g, W2g, b20f, b21f, uu, c1, c2, p0[4], p1[4]);
    }
    if (half == 0) {
#pragma unroll
        for (int k = 0; k < 5; ++k) op[k] = fpack(p0[k], p1[k]);
    }

    // eager accumulators: acc[k] = z(5+k) partial, EXCLUDING all pred(4) terms
    // (the main loop supplies those via o_prev, starting at t=5).
    ull P0[4], P1[4];
#pragma unroll
    for (int j = 0; j < 4; ++j) { P0[j] = fpack(p0[j], p0[j]); P1[j] = fpack(p1[j], p1[j]); }
    ull acc_p[5]; float acc_s[5];
#pragma unroll
    for (int k = 0; k < 5; ++k) {
        ull ap = w.b1_p; float as = w.b1_s;
#pragma unroll
        for (int i = 0; i < 5; ++i) {
            ap = f2fma(w.wu_p[i], pu[5 + k + i], ap);
            as = fmaf(w.wu_s[i], flow(pu[5 + k + i]), as);
        }
#pragma unroll
        for (int j = 0; j < 4; ++j) {
            if (j >= k) {
                int pos = j - k;
                ap = f2fma(w.wc1_p[pos], P0[j], ap);
                ap = f2fma(w.wc2_p[pos], P1[j], ap);
                as = fmaf(w.wc1_s[pos], p0[j], fmaf(w.wc2_s[pos], p1[j], as));
            }
        }
        acc_p[k] = ap; acc_s[k] = as;
    }

    // u ring: uq[j] = (u(10+j))x2
    ull uq[10];
#pragma unroll
    for (int j = 0; j < 10; ++j) uq[j] = pu[10 + j];

    // carried prediction: o_prev = pred(4)
    float o0 = p0[4], o1 = p1[4];
    ull cp1 = fpack(o0, o0), cp2 = fpack(o1, o1);

    // main loop: t = base + J, covers t = 5..1024; stores predicated to t < 1019.
    const ull* up = g_uD + (size_t)20 * Bsz + b;  // up[J*Bsz] = u(base + J + 15)
    ull* opd = op + 5;
    for (int base = 5; base < 1025; base += 10) {
        step<0>(acc_p, acc_s, uq, w, up, opd, base, half, o0, o1, cp1, cp2);
        step<1>(acc_p, acc_s, uq, w, up, opd, base, half, o0, o1, cp1, cp2);
        step<2>(acc_p, acc_s, uq, w, up, opd, base, half, o0, o1, cp1, cp2);
        step<3>(acc_p, acc_s, uq, w, up, opd, base, half, o0, o1, cp1, cp2);
        step<4>(acc_p, acc_s, uq, w, up, opd, base, half, o0, o1, cp1, cp2);
        step<5>(acc_p, acc_s, uq, w, up, opd, base, half, o0, o1, cp1, cp2);
        step<6>(acc_p, acc_s, uq, w, up, opd, base, half, o0, o1, cp1, cp2);
        step<7>(acc_p, acc_s, uq, w, up, opd, base, half, o0, o1, cp1, cp2);
        step<8>(acc_p, acc_s, uq, w, up, opd, base, half, o0, o1, cp1, cp2);
        step<9>(acc_p, acc_s, uq, w, up, opd, base, half, o0, o1, cp1, cp2);
        up += (size_t)10 * Bsz;
        opd += 10;
    }
}

extern "C" void kernel_launch(void* const* d_in, const int* in_sizes, int n_in,
                              void* d_out, int out_size) {
    (void)in_sizes; (void)n_in; (void)out_size;
    const float* traj = (const float*)d_in[0];
    const float* W1   = (const float*)d_in[1];
    const float* b1   = (const float*)d_in[2];
    const float* W2   = (const float*)d_in[3];
    const float* b2   = (const float*)d_in[4];

    transpose_u<<<dim3(Tlen / 32, Bsz / 32), dim3(32, 32)>>>(traj);
    rollout<<<(2 * Bsz) / 128, 128>>>(traj, W1, b1, W2, b2, (float*)d_out);
}